// round 1
// baseline (speedup 1.0000x reference)
#include <cuda_runtime.h>
#include <cstdint>

// Problem dims
constexpr int NB = 256;    // batch
constexpr int NT = 512;    // time
constexpr int NF = 256;    // features
constexpr int NH = 1024;   // hidden
constexpr int NG = 4096;   // 4*H
constexpr int NKD = NH + NF; // 1280, GEMM K for fused [h|x_t] @ [[U];[W]]
constexpr int NOUT = 64;

// Step-GEMM tiling
constexpr int BM = 64, BN = 128, BK = 16;
constexpr int NKT = NKD / BK; // 80
constexpr int AS_S = 20;      // As row stride (floats), 20 % 8 == 4 -> conflict-free frag reads
constexpr int BS_S = 136;     // Bs row stride, 136 % 32 == 8 -> conflict-free frag reads
constexpr int ZS_S = 136;

// ---------------- device scratch (allocation-free contract) ----------------
__device__ float g_M[NKD * NG];          // 20 MB: interleaved, tf32-rounded [[U];[W]]
__device__ float g_bI[NG];               // interleaved bias
__device__ float g_MLP[2048 * NH];       // 8 MB: [W1a+W1b ; W1c]
__device__ float g_h[2][NB * NH];        // ping-pong hidden state
__device__ float g_c[NB * NH];           // cell state
__device__ float g_y1[NB * NH];          // MLP hidden
__device__ unsigned char g_mask[NB * NT];

// ---------------- helpers ----------------
__device__ __forceinline__ unsigned tf32u(float f) {
    unsigned u;
    asm("cvt.rna.tf32.f32 %0, %1;" : "=r"(u) : "f"(f));
    return u;
}
__device__ __forceinline__ float to_tf32f(float x) {
    float y;
    asm("cvt.rna.tf32.f32 %0, %1;" : "=f"(y) : "f"(x));
    return y;
}
__device__ __forceinline__ float fex2(float x) {
    float y; asm("ex2.approx.f32 %0, %1;" : "=f"(y) : "f"(x)); return y;
}
__device__ __forceinline__ float frcp(float x) {
    float y; asm("rcp.approx.f32 %0, %1;" : "=f"(y) : "f"(x)); return y;
}
__device__ __forceinline__ float sigmf(float x) {
    // 1/(1+e^-x) via ex2+rcp (err ~1e-6)
    return frcp(1.0f + fex2(-1.4426950408889634f * x));
}
__device__ __forceinline__ float tanhfa(float x) {
    // 1 - 2/(1+e^{2x}); saturates correctly at +/-inf
    return 1.0f - 2.0f * frcp(1.0f + fex2(2.8853900817779268f * x));
}
__device__ __forceinline__ void cp16(float* dst, const float* src) {
    unsigned d = (unsigned)__cvta_generic_to_shared(dst);
    asm volatile("cp.async.cg.shared.global [%0], [%1], 16;" :: "r"(d), "l"(src));
}
__device__ __forceinline__ void mma8(float* d, const unsigned* a, const unsigned* b) {
    asm volatile(
        "mma.sync.aligned.m16n8k8.row.col.f32.tf32.tf32.f32 "
        "{%0,%1,%2,%3}, {%4,%5,%6,%7}, {%8,%9}, {%0,%1,%2,%3};"
        : "+f"(d[0]), "+f"(d[1]), "+f"(d[2]), "+f"(d[3])
        : "r"(a[0]), "r"(a[1]), "r"(a[2]), "r"(a[3]), "r"(b[0]), "r"(b[1]));
}

// ---------------- prep kernels (run every launch; deterministic) ----------------
// g_M[k][4j+g] = (k<NH ? U[k][g*NH+j] : W[k-NH][g*NH+j]), tf32-rounded.
__global__ void __launch_bounds__(256) prep_weights(
    const float* __restrict__ W, const float* __restrict__ U, const float* __restrict__ b) {
    int idx = blockIdx.x * 256 + threadIdx.x;
    if (idx >= NKD * NG) return;
    int k = idx >> 12;
    int jc = idx & (NG - 1);
    int gate = jc & 3;
    int j = jc >> 2;
    float v = (k < NH) ? U[(long)k * NG + gate * NH + j]
                       : W[(long)(k - NH) * NG + gate * NH + j];
    g_M[idx] = to_tf32f(v);
    if (idx < NG) g_bI[idx] = b[gate * NH + j];
}

// g_MLP rows 0..1023 = W1[0:1024]+W1[1024:2048]; rows 1024..2047 = W1[2048:3072]
__global__ void __launch_bounds__(256) prep_mlp(const float* __restrict__ W1) {
    int idx = blockIdx.x * 256 + threadIdx.x; // 2048*1024
    int k = idx >> 10, m = idx & (NH - 1);
    float v = (k < NH) ? (W1[(long)k * NH + m] + W1[(long)(k + NH) * NH + m])
                       : W1[(long)(k + NH) * NH + m];
    g_MLP[idx] = v;
}

__global__ void __launch_bounds__(256) init_state() {
    int idx = blockIdx.x * 256 + threadIdx.x; // NB*NH = 262144
    g_h[0][idx] = 0.0f;
    g_c[idx] = 0.0f;
}

// mask[b*T+t] = any(x[b,t,:] != 0); one warp per row
__global__ void __launch_bounds__(256) mask_kernel(const float* __restrict__ x) {
    int warp = (blockIdx.x * 256 + threadIdx.x) >> 5;
    int lane = threadIdx.x & 31;
    if (warp >= NB * NT) return;
    const float4* p = (const float4*)(x + (long)warp * NF);
    float4 v1 = p[lane];
    float4 v2 = p[lane + 32];
    bool nz = v1.x != 0.f || v1.y != 0.f || v1.z != 0.f || v1.w != 0.f ||
              v2.x != 0.f || v2.y != 0.f || v2.z != 0.f || v2.w != 0.f;
    unsigned m = __ballot_sync(0xffffffffu, nz);
    if (lane == 0) g_mask[warp] = (m != 0u);
}

// ---------------- fused LSTM step: z = [h|x_t] @ M + bI, gates, state update --------
__global__ void __launch_bounds__(256) lstm_step_kernel(const float* __restrict__ x, int t) {
    __shared__ float smem[8704]; // 34816 B; reused as z tile in epilogue
    float* As0 = smem;                 // [BM][AS_S]
    float* As1 = smem + BM * AS_S;     // +1280
    float* Bs0 = smem + 2 * BM * AS_S; // +2560, [BK][BS_S]
    float* Bs1 = Bs0 + BK * BS_S;      // +2176

    const int tid = threadIdx.x;
    const int lane = tid & 31;
    const int w = tid >> 5;
    const int wm = w & 1;   // 2 warps over M
    const int wn = w >> 1;  // 4 warps over N
    const int bn = blockIdx.x * BN;
    const int bm = blockIdx.y * BM;
    const int cur = t & 1;
    const float* __restrict__ hsrc = g_h[cur];

    float acc[2][4][4];
#pragma unroll
    for (int i = 0; i < 2; ++i)
#pragma unroll
        for (int j = 0; j < 4; ++j)
#pragma unroll
            for (int k = 0; k < 4; ++k) acc[i][j][k] = 0.0f;

    const int a_m = tid >> 2, a_kq = tid & 3; // A: 64x16, 1 float4/thread
    const int b_kr = tid >> 5, b_c4 = tid & 31; // B: 16x128, 2 float4/thread

    auto load_tiles = [&](int kt, float* Ad, float* Bd) {
        int k0 = kt * BK;
        int ka = k0 + 4 * a_kq;
        const float* asrc = (ka < NH)
            ? (hsrc + (long)(bm + a_m) * NH + ka)
            : (x + ((long)(bm + a_m) * NT + t) * NF + (ka - NH));
        cp16(Ad + a_m * AS_S + 4 * a_kq, asrc);
        const float* bsrc = g_M + (long)(k0 + b_kr) * NG + bn + 4 * b_c4;
        cp16(Bd + b_kr * BS_S + 4 * b_c4, bsrc);
        cp16(Bd + (b_kr + 8) * BS_S + 4 * b_c4, bsrc + (long)8 * NG);
        asm volatile("cp.async.commit_group;");
    };

    load_tiles(0, As0, Bs0);

    for (int kt = 0; kt < NKT; ++kt) {
        float* Ac = (kt & 1) ? As1 : As0;
        float* Bcur = (kt & 1) ? Bs1 : Bs0;
        if (kt + 1 < NKT) {
            load_tiles(kt + 1, (kt & 1) ? As0 : As1, (kt & 1) ? Bs0 : Bs1);
            asm volatile("cp.async.wait_group 1;");
        } else {
            asm volatile("cp.async.wait_group 0;");
        }
        __syncthreads();

        const int g = lane >> 2, c = lane & 3;
#pragma unroll
        for (int ks = 0; ks < 2; ++ks) {
            const int k0 = ks * 8;
            unsigned afr[2][4];
#pragma unroll
            for (int mt = 0; mt < 2; ++mt) {
                int rm = wm * 32 + mt * 16 + g;
                afr[mt][0] = tf32u(Ac[rm * AS_S + k0 + c]);
                afr[mt][1] = tf32u(Ac[(rm + 8) * AS_S + k0 + c]);
                afr[mt][2] = tf32u(Ac[rm * AS_S + k0 + c + 4]);
                afr[mt][3] = tf32u(Ac[(rm + 8) * AS_S + k0 + c + 4]);
            }
            unsigned bfr[4][2];
#pragma unroll
            for (int nt = 0; nt < 4; ++nt) {
                int cn = wn * 32 + nt * 8 + g;
                bfr[nt][0] = __float_as_uint(Bcur[(k0 + c) * BS_S + cn]);
                bfr[nt][1] = __float_as_uint(Bcur[(k0 + c + 4) * BS_S + cn]);
            }
#pragma unroll
            for (int mt = 0; mt < 2; ++mt)
#pragma unroll
                for (int nt = 0; nt < 4; ++nt) mma8(acc[mt][nt], afr[mt], bfr[nt]);
        }
        __syncthreads();
    }

    // park z tile in smem (gate-interleaved columns) for the fused epilogue
    float* zs = smem; // [BM][ZS_S]
    {
        const int g = lane >> 2, c2 = 2 * (lane & 3);
#pragma unroll
        for (int mt = 0; mt < 2; ++mt)
#pragma unroll
            for (int nt = 0; nt < 4; ++nt) {
                int r0 = wm * 32 + mt * 16 + g;
                int c0 = wn * 32 + nt * 8 + c2;
                zs[r0 * ZS_S + c0] = acc[mt][nt][0];
                zs[r0 * ZS_S + c0 + 1] = acc[mt][nt][1];
                zs[(r0 + 8) * ZS_S + c0] = acc[mt][nt][2];
                zs[(r0 + 8) * ZS_S + c0 + 1] = acc[mt][nt][3];
            }
    }
    __syncthreads();

    float* __restrict__ hdst = g_h[cur ^ 1];
#pragma unroll
    for (int it = 0; it < 8; ++it) {
        int idx = it * 256 + tid;
        int bl = idx >> 5;  // local batch row 0..63
        int u = idx & 31;   // local unit 0..31
        int bg = bm + bl;
        int j = (bn >> 2) + u;
        float4 z = *(float4*)(zs + bl * ZS_S + 4 * u);
        float4 bb = *(const float4*)(g_bI + bn + 4 * u);
        float iv = sigmf(z.x + bb.x);
        float fv = sigmf(z.y + bb.y);
        float gv = tanhfa(z.z + bb.z);
        float ov = sigmf(z.w + bb.w);
        long off = (long)bg * NH + j;
        float co = g_c[off];
        float ho = hsrc[off];
        float cn = fv * co + iv * gv;
        float hn = ov * tanhfa(cn);
        if (!g_mask[bg * NT + t]) { cn = co; hn = ho; }
        g_c[off] = cn;
        hdst[off] = hn;
    }
}

// ---------------- MLP head ----------------
// y1 = leaky( [h|c] @ g_MLP + b1 ), fp32 tiled GEMM, M=256 N=1024 K=2048
__global__ void __launch_bounds__(256) mlp1_kernel(const float* __restrict__ b1) {
    __shared__ float a_s[64 * 20];
    __shared__ float b_s[16 * 68];
    int tid = threadIdx.x;
    int bn = blockIdx.x * 64, bm = blockIdx.y * 64;
    int ty = tid >> 4, tx = tid & 15;
    float acc[4][4];
#pragma unroll
    for (int i = 0; i < 4; ++i)
#pragma unroll
        for (int j = 0; j < 4; ++j) acc[i][j] = 0.0f;

    for (int kt = 0; kt < 128; ++kt) {
        int k0 = kt * 16;
        {
            int m = tid >> 2, kq = tid & 3;
            int k = k0 + 4 * kq;
            const float* src = (k < NH) ? (g_h[0] + (long)(bm + m) * NH + k)
                                        : (g_c + (long)(bm + m) * NH + (k - NH));
            *(float4*)(a_s + m * 20 + 4 * kq) = *(const float4*)src;
        }
        {
            int kr = tid >> 4, c4 = tid & 15;
            *(float4*)(b_s + kr * 68 + 4 * c4) =
                *(const float4*)(g_MLP + (long)(k0 + kr) * NH + bn + 4 * c4);
        }
        __syncthreads();
#pragma unroll
        for (int k = 0; k < 16; ++k) {
            float ar[4], br[4];
#pragma unroll
            for (int i = 0; i < 4; ++i) {
                ar[i] = a_s[(4 * ty + i) * 20 + k];
                br[i] = b_s[k * 68 + 4 * tx + i];
            }
#pragma unroll
            for (int i = 0; i < 4; ++i)
#pragma unroll
                for (int j = 0; j < 4; ++j) acc[i][j] += ar[i] * br[j];
        }
        __syncthreads();
    }
#pragma unroll
    for (int i = 0; i < 4; ++i)
#pragma unroll
        for (int j = 0; j < 4; ++j) {
            float v = acc[i][j] + b1[bn + 4 * tx + j];
            v = v > 0.0f ? v : 0.2f * v;
            g_y1[(long)(bm + 4 * ty + i) * NH + bn + 4 * tx + j] = v;
        }
}

// y = y1 @ W2 + b2   (256x64, K=1024)
__global__ void __launch_bounds__(64) mlp2_kernel(
    const float* __restrict__ W2, const float* __restrict__ b2, float* __restrict__ out) {
    __shared__ float row[NH];
    int bg = blockIdx.x;
    int o = threadIdx.x;
    for (int i = o; i < NH; i += 64) row[i] = g_y1[(long)bg * NH + i];
    __syncthreads();
    float acc = b2[o];
#pragma unroll 8
    for (int k = 0; k < NH; ++k) acc += row[k] * W2[(long)k * NOUT + o];
    out[(long)bg * NOUT + o] = acc;
}

// ---------------- launch ----------------
extern "C" void kernel_launch(void* const* d_in, const int* in_sizes, int n_in,
                              void* d_out, int out_size) {
    const float* x  = (const float*)d_in[0];
    const float* W  = (const float*)d_in[1];
    const float* U  = (const float*)d_in[2];
    const float* b  = (const float*)d_in[3];
    const float* W1 = (const float*)d_in[4];
    const float* b1 = (const float*)d_in[5];
    const float* W2 = (const float*)d_in[6];
    const float* b2 = (const float*)d_in[7];
    float* out = (float*)d_out;

    prep_weights<<<(NKD * NG) / 256, 256>>>(W, U, b);
    prep_mlp<<<(2048 * NH) / 256, 256>>>(W1);
    init_state<<<(NB * NH) / 256, 256>>>();
    mask_kernel<<<(NB * NT * 32) / 256, 256>>>(x);
    for (int t = 0; t < NT; ++t)
        lstm_step_kernel<<<dim3(NG / BN, NB / BM), 256>>>(x, t);
    mlp1_kernel<<<dim3(NH / 64, NB / 64), 256>>>(b1);
    mlp2_kernel<<<NB, 64>>>(W2, b2, out);
}

// round 2
// speedup vs baseline: 1.2174x; 1.2174x over previous
#include <cuda_runtime.h>
#include <cstdint>

// Problem dims
constexpr int NB = 256;    // batch
constexpr int NT = 512;    // time
constexpr int NF = 256;    // features
constexpr int NH = 1024;   // hidden
constexpr int NG = 4096;   // 4*H
constexpr int NKD = NH + NF; // 1280 = GEMM K for fused [h|x_t] @ [[U];[W]]
constexpr int NOUT = 64;

// Step-GEMM tiling (persistent kernel)
constexpr int BM = 64, BN = 128, BK = 32;
constexpr int NKT = NKD / BK;  // 40
constexpr int NSTAGE = 3;
constexpr int AS_S = 36;       // A row stride (36 % 8 == 4 -> conflict-free frag reads)
constexpr int BS_S = 136;      // B row stride (136 % 32 == 8 -> conflict-free frag reads)
constexpr int ZS_S = 136;
constexpr int AS_SZ = BM * AS_S;   // 2304 floats / stage
constexpr int BS_SZ = BK * BS_S;   // 4352 floats / stage
constexpr int SMEM_FLOATS = NSTAGE * (AS_SZ + BS_SZ) + BM * ZS_S; // 28672
constexpr int SMEM_BYTES = SMEM_FLOATS * 4;                       // 114688
constexpr int NCTAS = (NG / BN) * (NB / BM); // 128

// ---------------- device scratch (allocation-free contract) ----------------
__device__ float g_M[NKD * NG];          // 20 MB: interleaved, tf32-rounded [[U];[W]]
__device__ float g_bI[NG];               // interleaved bias
__device__ float g_MLP[2048 * NH];       // 8 MB: [W1a+W1b ; W1c]
__device__ float g_h[2][NB * NH];        // ping-pong hidden state
__device__ float g_c[NB * NH];           // cell state
__device__ float g_y1[NB * NH];          // MLP hidden
__device__ unsigned char g_mask[NB * NT];
__device__ unsigned g_bar = 0;           // grid barrier arrive counter
__device__ unsigned g_gen = 0;           // grid barrier generation

// ---------------- helpers ----------------
__device__ __forceinline__ unsigned tf32u(float f) {
    unsigned u;
    asm("cvt.rna.tf32.f32 %0, %1;" : "=r"(u) : "f"(f));
    return u;
}
__device__ __forceinline__ float to_tf32f(float x) {
    float y;
    asm("cvt.rna.tf32.f32 %0, %1;" : "=f"(y) : "f"(x));
    return y;
}
__device__ __forceinline__ float fex2(float x) {
    float y; asm("ex2.approx.f32 %0, %1;" : "=f"(y) : "f"(x)); return y;
}
__device__ __forceinline__ float frcp(float x) {
    float y; asm("rcp.approx.f32 %0, %1;" : "=f"(y) : "f"(x)); return y;
}
__device__ __forceinline__ float sigmf(float x) {
    return frcp(1.0f + fex2(-1.4426950408889634f * x));
}
__device__ __forceinline__ float tanhfa(float x) {
    return 1.0f - 2.0f * frcp(1.0f + fex2(2.8853900817779268f * x));
}
__device__ __forceinline__ void cp16(float* dst, const float* src) {
    unsigned d = (unsigned)__cvta_generic_to_shared(dst);
    asm volatile("cp.async.cg.shared.global [%0], [%1], 16;" :: "r"(d), "l"(src));
}
__device__ __forceinline__ void mma8(float* d, const unsigned* a, const unsigned* b) {
    asm volatile(
        "mma.sync.aligned.m16n8k8.row.col.f32.tf32.tf32.f32 "
        "{%0,%1,%2,%3}, {%4,%5,%6,%7}, {%8,%9}, {%0,%1,%2,%3};"
        : "+f"(d[0]), "+f"(d[1]), "+f"(d[2]), "+f"(d[3])
        : "r"(a[0]), "r"(a[1]), "r"(a[2]), "r"(a[3]), "r"(b[0]), "r"(b[1]));
}

// Release/acquire grid barrier. Safe: all 128 CTAs are co-resident
// (112 KB smem/CTA -> 1 CTA/SM, 128 <= 148 SMs).
__device__ __forceinline__ void grid_barrier() {
    __syncthreads();
    if (threadIdx.x == 0) {
        unsigned gen = *(volatile unsigned*)&g_gen;
        __threadfence();                       // release h/c stores
        if (atomicAdd(&g_bar, 1u) == NCTAS - 1) {
            atomicExch(&g_bar, 0u);
            __threadfence();
            atomicAdd(&g_gen, 1u);
        } else {
            while (*(volatile unsigned*)&g_gen == gen) __nanosleep(64);
        }
        __threadfence();                       // acquire
    }
    __syncthreads();
}

// ---------------- prep kernels ----------------
__global__ void __launch_bounds__(256) prep_weights(
    const float* __restrict__ W, const float* __restrict__ U, const float* __restrict__ b) {
    int idx = blockIdx.x * 256 + threadIdx.x;
    if (idx >= NKD * NG) return;
    int k = idx >> 12;
    int jc = idx & (NG - 1);
    int gate = jc & 3;
    int j = jc >> 2;
    float v = (k < NH) ? U[(long)k * NG + gate * NH + j]
                       : W[(long)(k - NH) * NG + gate * NH + j];
    g_M[idx] = to_tf32f(v);
    if (idx < NG) g_bI[idx] = b[gate * NH + j];
}

__global__ void __launch_bounds__(256) prep_mlp(const float* __restrict__ W1) {
    int idx = blockIdx.x * 256 + threadIdx.x; // 2048*1024
    int k = idx >> 10, m = idx & (NH - 1);
    float v = (k < NH) ? (W1[(long)k * NH + m] + W1[(long)(k + NH) * NH + m])
                       : W1[(long)(k + NH) * NH + m];
    g_MLP[idx] = v;
}

__global__ void __launch_bounds__(256) init_state() {
    int idx = blockIdx.x * 256 + threadIdx.x; // NB*NH
    g_h[0][idx] = 0.0f;
    g_c[idx] = 0.0f;
}

__global__ void __launch_bounds__(256) mask_kernel(const float* __restrict__ x) {
    int warp = (blockIdx.x * 256 + threadIdx.x) >> 5;
    int lane = threadIdx.x & 31;
    if (warp >= NB * NT) return;
    const float4* p = (const float4*)(x + (long)warp * NF);
    float4 v1 = p[lane];
    float4 v2 = p[lane + 32];
    bool nz = v1.x != 0.f || v1.y != 0.f || v1.z != 0.f || v1.w != 0.f ||
              v2.x != 0.f || v2.y != 0.f || v2.z != 0.f || v2.w != 0.f;
    unsigned m = __ballot_sync(0xffffffffu, nz);
    if (lane == 0) g_mask[warp] = (m != 0u);
}

// ---------------- persistent LSTM recurrence ----------------
__global__ void __launch_bounds__(256) lstm_persistent(const float* __restrict__ x) {
    extern __shared__ float dsm[];
    float* As = dsm;                       // 3 stages x [64][36]
    float* Bsm = dsm + NSTAGE * AS_SZ;     // 3 stages x [32][136]
    float* zs = Bsm + NSTAGE * BS_SZ;      // [64][136]

    const int tid = threadIdx.x;
    const int lane = tid & 31;
    const int w = tid >> 5;
    const int wm = w & 1;   // 2 warps over M
    const int wn = w >> 1;  // 4 warps over N
    const int bn = blockIdx.x * BN;
    const int bm = blockIdx.y * BM;

    // load-thread mappings
    const int a_m = tid >> 3, a_q = tid & 7;   // A: 2 rows/thread (a_m, a_m+32)
    const int b_r = tid >> 5, b_c = tid & 31;  // B: 4 rows/thread (b_r + 8i)

    auto loadB = [&](int kt, int s) {
        float* Bd = Bsm + s * BS_SZ;
        const float* bsrc = g_M + (long)(kt * BK + b_r) * NG + bn + 4 * b_c;
#pragma unroll
        for (int r = 0; r < 4; ++r)
            cp16(Bd + (b_r + 8 * r) * BS_S + 4 * b_c, bsrc + (long)(8 * r) * NG);
    };
    auto loadA = [&](int kt, int s, const float* hsrc, int t) {
        float* Ad = As + s * AS_SZ;
        int gk = kt * BK + 4 * a_q;
#pragma unroll
        for (int r = 0; r < 2; ++r) {
            int row = a_m + 32 * r;
            const float* src = (gk < NH)
                ? (hsrc + (long)(bm + row) * NH + gk)
                : (x + ((long)(bm + row) * NT + t) * NF + (gk - NH));
            cp16(Ad + row * AS_S + 4 * a_q, src);
        }
    };

    // pre-loop: prefetch B for t=0, stages 0 and 1 (uncommitted)
    loadB(0, 0);
    loadB(1, 1);

    for (int t = 0; t < NT; ++t) {
        const int cur = t & 1;
        const float* __restrict__ hsrc = g_h[cur];
        float* __restrict__ hdst = g_h[cur ^ 1];

        // prologue: A for stages 0,1 (B already prefetched pre-barrier)
        loadA(0, 0, hsrc, t);
        asm volatile("cp.async.commit_group;");
        loadA(1, 1, hsrc, t);
        asm volatile("cp.async.commit_group;");

        float acc[2][4][4];
#pragma unroll
        for (int i = 0; i < 2; ++i)
#pragma unroll
            for (int j = 0; j < 4; ++j)
#pragma unroll
                for (int k = 0; k < 4; ++k) acc[i][j][k] = 0.0f;

        for (int kt = 0; kt < NKT; ++kt) {
            if (kt + 2 < NKT) {
                int s = (kt + 2) % NSTAGE;
                loadA(kt + 2, s, hsrc, t);
                loadB(kt + 2, s);
                asm volatile("cp.async.commit_group;");
                asm volatile("cp.async.wait_group 2;");
            } else if (kt + 1 < NKT) {
                asm volatile("cp.async.wait_group 1;");
            } else {
                asm volatile("cp.async.wait_group 0;");
            }
            __syncthreads();

            const float* Ac = As + (kt % NSTAGE) * AS_SZ;
            const float* Bc = Bsm + (kt % NSTAGE) * BS_SZ;
            const int g = lane >> 2, c = lane & 3;
#pragma unroll
            for (int ks = 0; ks < 4; ++ks) {
                const int k0 = ks * 8;
                unsigned afr[2][4];
#pragma unroll
                for (int mt = 0; mt < 2; ++mt) {
                    int rm = wm * 32 + mt * 16 + g;
                    afr[mt][0] = tf32u(Ac[rm * AS_S + k0 + c]);
                    afr[mt][1] = tf32u(Ac[(rm + 8) * AS_S + k0 + c]);
                    afr[mt][2] = tf32u(Ac[rm * AS_S + k0 + c + 4]);
                    afr[mt][3] = tf32u(Ac[(rm + 8) * AS_S + k0 + c + 4]);
                }
                unsigned bfr[4][2];
#pragma unroll
                for (int nt = 0; nt < 4; ++nt) {
                    int cn = wn * 32 + nt * 8 + g;
                    bfr[nt][0] = __float_as_uint(Bc[(k0 + c) * BS_S + cn]);
                    bfr[nt][1] = __float_as_uint(Bc[(k0 + c + 4) * BS_S + cn]);
                }
#pragma unroll
                for (int mt = 0; mt < 2; ++mt)
#pragma unroll
                    for (int nt = 0; nt < 4; ++nt) mma8(acc[mt][nt], afr[mt], bfr[nt]);
            }
            __syncthreads();
        }

        // prefetch next step's B (t-independent weights) into stages 0,1
        // BEFORE the grid barrier — hides epilogue + barrier latency.
        if (t + 1 < NT) {
            loadB(0, 0);
            loadB(1, 1);
        }

        // park z tile (gate-interleaved columns) in dedicated smem
        {
            const int g = lane >> 2, c2 = 2 * (lane & 3);
#pragma unroll
            for (int mt = 0; mt < 2; ++mt)
#pragma unroll
                for (int nt = 0; nt < 4; ++nt) {
                    int r0 = wm * 32 + mt * 16 + g;
                    int c0 = wn * 32 + nt * 8 + c2;
                    zs[r0 * ZS_S + c0] = acc[mt][nt][0];
                    zs[r0 * ZS_S + c0 + 1] = acc[mt][nt][1];
                    zs[(r0 + 8) * ZS_S + c0] = acc[mt][nt][2];
                    zs[(r0 + 8) * ZS_S + c0 + 1] = acc[mt][nt][3];
                }
        }
        __syncthreads();

        // fused gate + state update epilogue
#pragma unroll
        for (int it = 0; it < 8; ++it) {
            int idx = it * 256 + tid;
            int bl = idx >> 5;  // local batch row 0..63
            int u = idx & 31;   // local unit 0..31
            int bg = bm + bl;
            int j = (bn >> 2) + u;
            float4 z = *(float4*)(zs + bl * ZS_S + 4 * u);
            float4 bb = *(const float4*)(g_bI + bn + 4 * u);
            float iv = sigmf(z.x + bb.x);
            float fv = sigmf(z.y + bb.y);
            float gv = tanhfa(z.z + bb.z);
            float ov = sigmf(z.w + bb.w);
            long off = (long)bg * NH + j;
            float co = g_c[off];
            float ho = hsrc[off];
            float cn = fv * co + iv * gv;
            float hn = ov * tanhfa(cn);
            if (!g_mask[bg * NT + t]) { cn = co; hn = ho; }
            g_c[off] = cn;
            hdst[off] = hn;
        }

        grid_barrier();
    }
}

// ---------------- MLP head ----------------
__global__ void __launch_bounds__(256) mlp1_kernel(const float* __restrict__ b1) {
    __shared__ float a_s[64 * 20];
    __shared__ float b_s[16 * 68];
    int tid = threadIdx.x;
    int bn = blockIdx.x * 64, bm = blockIdx.y * 64;
    int ty = tid >> 4, tx = tid & 15;
    float acc[4][4];
#pragma unroll
    for (int i = 0; i < 4; ++i)
#pragma unroll
        for (int j = 0; j < 4; ++j) acc[i][j] = 0.0f;

    for (int kt = 0; kt < 128; ++kt) {
        int k0 = kt * 16;
        {
            int m = tid >> 2, kq = tid & 3;
            int k = k0 + 4 * kq;
            const float* src = (k < NH) ? (g_h[0] + (long)(bm + m) * NH + k)
                                        : (g_c + (long)(bm + m) * NH + (k - NH));
            *(float4*)(a_s + m * 20 + 4 * kq) = *(const float4*)src;
        }
        {
            int kr = tid >> 4, c4 = tid & 15;
            *(float4*)(b_s + kr * 68 + 4 * c4) =
                *(const float4*)(g_MLP + (long)(k0 + kr) * NH + bn + 4 * c4);
        }
        __syncthreads();
#pragma unroll
        for (int k = 0; k < 16; ++k) {
            float ar[4], br[4];
#pragma unroll
            for (int i = 0; i < 4; ++i) {
                ar[i] = a_s[(4 * ty + i) * 20 + k];
                br[i] = b_s[k * 68 + 4 * tx + i];
            }
#pragma unroll
            for (int i = 0; i < 4; ++i)
#pragma unroll
                for (int j = 0; j < 4; ++j) acc[i][j] += ar[i] * br[j];
        }
        __syncthreads();
    }
#pragma unroll
    for (int i = 0; i < 4; ++i)
#pragma unroll
        for (int j = 0; j < 4; ++j) {
            float v = acc[i][j] + b1[bn + 4 * tx + j];
            v = v > 0.0f ? v : 0.2f * v;
            g_y1[(long)(bm + 4 * ty + i) * NH + bn + 4 * tx + j] = v;
        }
}

__global__ void __launch_bounds__(64) mlp2_kernel(
    const float* __restrict__ W2, const float* __restrict__ b2, float* __restrict__ out) {
    __shared__ float row[NH];
    int bg = blockIdx.x;
    int o = threadIdx.x;
    for (int i = o; i < NH; i += 64) row[i] = g_y1[(long)bg * NH + i];
    __syncthreads();
    float acc = b2[o];
#pragma unroll 8
    for (int k = 0; k < NH; ++k) acc += row[k] * W2[(long)k * NOUT + o];
    out[(long)bg * NOUT + o] = acc;
}

// ---------------- launch ----------------
extern "C" void kernel_launch(void* const* d_in, const int* in_sizes, int n_in,
                              void* d_out, int out_size) {
    const float* x  = (const float*)d_in[0];
    const float* W  = (const float*)d_in[1];
    const float* U  = (const float*)d_in[2];
    const float* b  = (const float*)d_in[3];
    const float* W1 = (const float*)d_in[4];
    const float* b1 = (const float*)d_in[5];
    const float* W2 = (const float*)d_in[6];
    const float* b2 = (const float*)d_in[7];
    float* out = (float*)d_out;

    cudaFuncSetAttribute(lstm_persistent,
                         cudaFuncAttributeMaxDynamicSharedMemorySize, SMEM_BYTES);

    prep_weights<<<(NKD * NG) / 256, 256>>>(W, U, b);
    prep_mlp<<<(2048 * NH) / 256, 256>>>(W1);
    init_state<<<(NB * NH) / 256, 256>>>();
    mask_kernel<<<(NB * NT * 32) / 256, 256>>>(x);
    lstm_persistent<<<dim3(NG / BN, NB / BM), 256, SMEM_BYTES>>>(x);
    mlp1_kernel<<<dim3(NH / 64, NB / 64), 256>>>(b1);
    mlp2_kernel<<<NB, 64>>>(W2, b2, out);
}

// round 4
// speedup vs baseline: 1.3453x; 1.1050x over previous
#include <cuda_runtime.h>
#include <cstdint>

// Problem dims
constexpr int NB = 256, NT = 512, NF = 256, NH = 1024, NG = 4096;
constexpr int NKD = NH + NF; // 1280
constexpr int NOUT = 64;

// Persistent step-GEMM tiling (mma.sync tf32 path; tcgen05 rejected by ptxas target sm_103)
constexpr int BM = 64, BN = 128, BK = 64;
constexpr int NKT = NKD / BK;  // 20
constexpr int NST = 3;
constexpr int AS_S = 68;       // A row stride (68 % 32 == 4 -> conflict-free frag reads)
constexpr int BS_S = 136;      // B row stride (136 % 32 == 8 -> conflict-free frag reads)
constexpr int ZS_S = 136;
constexpr int A_FL = BM * AS_S;        // 4352 floats
constexpr int B_FL = BK * BS_S;        // 8704 floats
constexpr int ST_FL = A_FL + B_FL;     // 13056 floats / stage
constexpr int SMEM_FLOATS = NST * ST_FL + BM * ZS_S; // 47872
constexpr int SMEM_BYTES = SMEM_FLOATS * 4;          // 191488
constexpr int NCTAS = (NB / BM) * (NG / BN);         // 128

// ---------------- device scratch (allocation-free contract) ----------------
__device__ float g_M[NKD * NG];          // 20 MB: interleaved, tf32-rounded [[U];[W]]
__device__ float g_bI[NG];               // interleaved bias
__device__ float g_xr[(long)NB * NT * NF]; // 134 MB: tf32-rounded x
__device__ float g_MLP[2048 * NH];       // [W1a+W1b ; W1c]
__device__ float g_h[2][NB * NH];        // ping-pong hidden (tf32-rounded)
__device__ float g_c[NB * NH];
__device__ float g_y1[NB * NH];
__device__ unsigned char g_mask[NB * NT];
__device__ unsigned g_bar = 0, g_gen = 0;

// ---------------- helpers ----------------
__device__ __forceinline__ float to_tf32f(float x) {
    float y;
    asm("cvt.rna.tf32.f32 %0, %1;" : "=f"(y) : "f"(x));
    return y;
}
__device__ __forceinline__ float fex2(float x) {
    float y; asm("ex2.approx.f32 %0, %1;" : "=f"(y) : "f"(x)); return y;
}
__device__ __forceinline__ float frcp(float x) {
    float y; asm("rcp.approx.f32 %0, %1;" : "=f"(y) : "f"(x)); return y;
}
__device__ __forceinline__ float sigmf(float x) {
    return frcp(1.0f + fex2(-1.4426950408889634f * x));
}
__device__ __forceinline__ float tanhfa(float x) {
    return 1.0f - 2.0f * frcp(1.0f + fex2(2.8853900817779268f * x));
}
__device__ __forceinline__ void cp16(float* dst, const float* src) {
    unsigned d = (unsigned)__cvta_generic_to_shared(dst);
    asm volatile("cp.async.cg.shared.global [%0], [%1], 16;" :: "r"(d), "l"(src));
}
__device__ __forceinline__ void cp_commit() {
    asm volatile("cp.async.commit_group;");
}
template <int N>
__device__ __forceinline__ void cp_wait() {
    asm volatile("cp.async.wait_group %0;" :: "n"(N));
}
__device__ __forceinline__ void mma8(float* d, const unsigned* a, const unsigned* b) {
    asm volatile(
        "mma.sync.aligned.m16n8k8.row.col.f32.tf32.tf32.f32 "
        "{%0,%1,%2,%3}, {%4,%5,%6,%7}, {%8,%9}, {%0,%1,%2,%3};"
        : "+f"(d[0]), "+f"(d[1]), "+f"(d[2]), "+f"(d[3])
        : "r"(a[0]), "r"(a[1]), "r"(a[2]), "r"(a[3]), "r"(b[0]), "r"(b[1]));
}

// grid barrier: 128 CTAs, all co-resident (1 CTA/SM at 187 KB smem)
__device__ __forceinline__ void grid_barrier() {
    __syncthreads();
    if (threadIdx.x == 0) {
        unsigned gen = *(volatile unsigned*)&g_gen;
        __threadfence();
        if (atomicAdd(&g_bar, 1u) == NCTAS - 1) {
            atomicExch(&g_bar, 0u);
            __threadfence();
            atomicAdd(&g_gen, 1u);
        } else {
            while (*(volatile unsigned*)&g_gen == gen) __nanosleep(64);
        }
        __threadfence();
    }
    __syncthreads();
}

// ---------------- prep kernels ----------------
// g_M[k][4j+g] = tf32( k<NH ? U[k][g*NH+j] : W[k-NH][g*NH+j] )
__global__ void __launch_bounds__(256) prep_weights(
    const float* __restrict__ W, const float* __restrict__ U, const float* __restrict__ b) {
    int idx = blockIdx.x * 256 + threadIdx.x;
    if (idx >= NKD * NG) return;
    int k = idx >> 12;
    int jc = idx & (NG - 1);
    int gate = jc & 3;
    int j = jc >> 2;
    float v = (k < NH) ? U[(long)k * NG + gate * NH + j]
                       : W[(long)(k - NH) * NG + gate * NH + j];
    g_M[idx] = to_tf32f(v);
    if (idx < NG) g_bI[idx] = b[gate * NH + j];
}

__global__ void __launch_bounds__(256) prep_x(const float* __restrict__ x) {
    long idx = (long)blockIdx.x * 256 + threadIdx.x;
    g_xr[idx] = to_tf32f(x[idx]);
}

__global__ void __launch_bounds__(256) prep_mlp(const float* __restrict__ W1) {
    int idx = blockIdx.x * 256 + threadIdx.x;
    int k = idx >> 10, m = idx & (NH - 1);
    float v = (k < NH) ? (W1[(long)k * NH + m] + W1[(long)(k + NH) * NH + m])
                       : W1[(long)(k + NH) * NH + m];
    g_MLP[idx] = v;
}

__global__ void __launch_bounds__(256) init_state() {
    int idx = blockIdx.x * 256 + threadIdx.x;
    g_h[0][idx] = 0.0f;
    g_c[idx] = 0.0f;
}

__global__ void __launch_bounds__(256) mask_kernel(const float* __restrict__ x) {
    int warp = (blockIdx.x * 256 + threadIdx.x) >> 5;
    int lane = threadIdx.x & 31;
    if (warp >= NB * NT) return;
    const float4* p = (const float4*)(x + (long)warp * NF);
    float4 v1 = p[lane];
    float4 v2 = p[lane + 32];
    bool nz = v1.x != 0.f || v1.y != 0.f || v1.z != 0.f || v1.w != 0.f ||
              v2.x != 0.f || v2.y != 0.f || v2.z != 0.f || v2.w != 0.f;
    unsigned m = __ballot_sync(0xffffffffu, nz);
    if (lane == 0) g_mask[warp] = (m != 0u);
}

// ---------------- persistent LSTM recurrence ----------------
__global__ void __launch_bounds__(256) lstm_persistent() {
    extern __shared__ float dsm[];
    float* zs = dsm + NST * ST_FL;  // [64][136], dedicated

    const int tid = threadIdx.x;
    const int lane = tid & 31;
    const int w = tid >> 5;
    const int wm = w & 1;   // 2 warps over M
    const int wn = w >> 1;  // 4 warps over N
    const int bn = blockIdx.x * BN;
    const int bm = blockIdx.y * BM;

    // loader mappings
    const int a_m = tid >> 2, a_q = tid & 3;   // A: row a_m, chunks a_q + 4i (i=0..3)
    const int b_r = tid >> 5, b_c = tid & 31;  // B: rows b_r + 8i (i=0..7), chunk b_c

    auto loadB = [&](int kt, int s) {
        float* Bd = dsm + s * ST_FL + A_FL;
        const float* bsrc = g_M + (long)(kt * BK + b_r) * NG + bn + 4 * b_c;
#pragma unroll
        for (int i = 0; i < 8; ++i)
            cp16(Bd + (b_r + 8 * i) * BS_S + 4 * b_c, bsrc + (long)(8 * i) * NG);
    };
    auto loadA = [&](int kt, int s, const float* hsrc, int t) {
        float* Ad = dsm + s * ST_FL;
#pragma unroll
        for (int i = 0; i < 4; ++i) {
            int kc = kt * BK + 4 * a_q + 16 * i;
            const float* src = (kc < NH)
                ? (hsrc + (long)(bm + a_m) * NH + kc)
                : (g_xr + ((long)(bm + a_m) * NT + t) * NF + (kc - NH));
            cp16(Ad + a_m * AS_S + 4 * a_q + 16 * i, src);
        }
    };

    // pre-loop: B for t=0 stages 0,1 in flight (uncommitted; folded into first commits)
    loadB(0, 0);
    loadB(1, 1);

    const int g = lane >> 2, c = lane & 3;

    for (int t = 0; t < NT; ++t) {
        const int cur = t & 1;
        const float* __restrict__ hsrc = g_h[cur];
        float* __restrict__ hdst = g_h[cur ^ 1];

        // prologue: A for stages 0,1 (B already in flight)
        loadA(0, 0, hsrc, t);
        cp_commit();                 // group(stage0) = {B0, B1, A0}
        loadA(1, 1, hsrc, t);
        cp_commit();                 // group(stage1) = {A1}

        float acc[2][4][4];
#pragma unroll
        for (int i = 0; i < 2; ++i)
#pragma unroll
            for (int j = 0; j < 4; ++j)
#pragma unroll
                for (int k = 0; k < 4; ++k) acc[i][j][k] = 0.0f;

        for (int kt = 0; kt < NKT; ++kt) {
            if (kt + 1 < NKT) cp_wait<1>(); else cp_wait<0>();
            __syncthreads();         // stage kt ready; stage (kt+2)%3 free for reuse

            const float* Ac = dsm + (kt % NST) * ST_FL;
            const float* Bc = Ac + A_FL;
#pragma unroll
            for (int ks = 0; ks < 8; ++ks) {
                const int k0 = ks * 8;
                unsigned afr[2][4];
#pragma unroll
                for (int mt = 0; mt < 2; ++mt) {
                    int rm = wm * 32 + mt * 16 + g;
                    afr[mt][0] = __float_as_uint(Ac[rm * AS_S + k0 + c]);
                    afr[mt][1] = __float_as_uint(Ac[(rm + 8) * AS_S + k0 + c]);
                    afr[mt][2] = __float_as_uint(Ac[rm * AS_S + k0 + c + 4]);
                    afr[mt][3] = __float_as_uint(Ac[(rm + 8) * AS_S + k0 + c + 4]);
                }
                unsigned bfr[4][2];
#pragma unroll
                for (int nt = 0; nt < 4; ++nt) {
                    int cn = wn * 32 + nt * 8 + g;
                    bfr[nt][0] = __float_as_uint(Bc[(k0 + c) * BS_S + cn]);
                    bfr[nt][1] = __float_as_uint(Bc[(k0 + c + 4) * BS_S + cn]);
                }
#pragma unroll
                for (int mt = 0; mt < 2; ++mt)
#pragma unroll
                    for (int nt = 0; nt < 4; ++nt) mma8(acc[mt][nt], afr[mt], bfr[nt]);
            }

            // issue next loads AFTER the sync: stage (kt+2)%3 was last read at kt-1,
            // all warps finished it before this iteration's sync -> race-free.
            if (kt + 2 < NKT) {
                loadA(kt + 2, (kt + 2) % NST, hsrc, t);
                loadB(kt + 2, (kt + 2) % NST);
                cp_commit();
            }
        }

        // park z tile (gate-interleaved cols); own accumulators, no sync needed yet
        {
            const int c2 = 2 * c;
#pragma unroll
            for (int mt = 0; mt < 2; ++mt)
#pragma unroll
                for (int nt = 0; nt < 4; ++nt) {
                    int r0 = wm * 32 + mt * 16 + g;
                    int c0 = wn * 32 + nt * 8 + c2;
                    zs[r0 * ZS_S + c0] = acc[mt][nt][0];
                    zs[r0 * ZS_S + c0 + 1] = acc[mt][nt][1];
                    zs[(r0 + 8) * ZS_S + c0] = acc[mt][nt][2];
                    zs[(r0 + 8) * ZS_S + c0 + 1] = acc[mt][nt][3];
                }
        }

        // next step's B prefetch: stage0 safe now (last read kt=18, guarded by sync@19);
        if (t + 1 < NT) loadB(0, 0);
        __syncthreads();  // z visible to all; also: all warps done with stage1 (kt=19)
        if (t + 1 < NT) loadB(1, 1);

        // fused gate + state update epilogue
#pragma unroll
        for (int it = 0; it < 8; ++it) {
            int idx = it * 256 + tid;
            int bl = idx >> 5;  // local batch row 0..63
            int u = idx & 31;   // local unit 0..31
            int bg = bm + bl;
            int j = (bn >> 2) + u;
            float4 z = *(float4*)(zs + bl * ZS_S + 4 * u);
            float4 bb = *(const float4*)(g_bI + bn + 4 * u);
            float iv = sigmf(z.x + bb.x);
            float fv = sigmf(z.y + bb.y);
            float gv = tanhfa(z.z + bb.z);
            float ov = sigmf(z.w + bb.w);
            long off = (long)bg * NH + j;
            float co = g_c[off];
            float ho = hsrc[off];
            float cn = fv * co + iv * gv;
            float hn = to_tf32f(ov * tanhfa(cn));  // pre-round: next GEMM input
            if (!g_mask[bg * NT + t]) { cn = co; hn = ho; }
            g_c[off] = cn;
            hdst[off] = hn;
        }

        grid_barrier();
    }
}

// ---------------- MLP head ----------------
__global__ void __launch_bounds__(256) mlp1_kernel(const float* __restrict__ b1) {
    __shared__ float a_s[64 * 20];
    __shared__ float b_s[16 * 68];
    int tid = threadIdx.x;
    int bn = blockIdx.x * 64, bm = blockIdx.y * 64;
    int ty = tid >> 4, tx = tid & 15;
    float acc[4][4];
#pragma unroll
    for (int i = 0; i < 4; ++i)
#pragma unroll
        for (int j = 0; j < 4; ++j) acc[i][j] = 0.0f;

    for (int kt = 0; kt < 128; ++kt) {
        int k0 = kt * 16;
        {
            int m = tid >> 2, kq = tid & 3;
            int k = k0 + 4 * kq;
            const float* src = (k < NH) ? (g_h[0] + (long)(bm + m) * NH + k)
                                        : (g_c + (long)(bm + m) * NH + (k - NH));
            *(float4*)(a_s + m * 20 + 4 * kq) = *(const float4*)src;
        }
        {
            int kr = tid >> 4, c4 = tid & 15;
            *(float4*)(b_s + kr * 68 + 4 * c4) =
                *(const float4*)(g_MLP + (long)(k0 + kr) * NH + bn + 4 * c4);
        }
        __syncthreads();
#pragma unroll
        for (int k = 0; k < 16; ++k) {
            float ar[4], br[4];
#pragma unroll
            for (int i = 0; i < 4; ++i) {
                ar[i] = a_s[(4 * ty + i) * 20 + k];
                br[i] = b_s[k * 68 + 4 * tx + i];
            }
#pragma unroll
            for (int i = 0; i < 4; ++i)
#pragma unroll
                for (int j = 0; j < 4; ++j) acc[i][j] += ar[i] * br[j];
        }
        __syncthreads();
    }
#pragma unroll
    for (int i = 0; i < 4; ++i)
#pragma unroll
        for (int j = 0; j < 4; ++j) {
            float v = acc[i][j] + b1[bn + 4 * tx + j];
            v = v > 0.0f ? v : 0.2f * v;
            g_y1[(long)(bm + 4 * ty + i) * NH + bn + 4 * tx + j] = v;
        }
}

__global__ void __launch_bounds__(64) mlp2_kernel(
    const float* __restrict__ W2, const float* __restrict__ b2, float* __restrict__ out) {
    __shared__ float row[NH];
    int bg = blockIdx.x;
    int o = threadIdx.x;
    for (int i = o; i < NH; i += 64) row[i] = g_y1[(long)bg * NH + i];
    __syncthreads();
    float acc = b2[o];
#pragma unroll 8
    for (int k = 0; k < NH; ++k) acc += row[k] * W2[(long)k * NOUT + o];
    out[(long)bg * NOUT + o] = acc;
}

// ---------------- launch ----------------
extern "C" void kernel_launch(void* const* d_in, const int* in_sizes, int n_in,
                              void* d_out, int out_size) {
    const float* x  = (const float*)d_in[0];
    const float* W  = (const float*)d_in[1];
    const float* U  = (const float*)d_in[2];
    const float* b  = (const float*)d_in[3];
    const float* W1 = (const float*)d_in[4];
    const float* b1 = (const float*)d_in[5];
    const float* W2 = (const float*)d_in[6];
    const float* b2 = (const float*)d_in[7];
    float* out = (float*)d_out;

    cudaFuncSetAttribute(lstm_persistent,
                         cudaFuncAttributeMaxDynamicSharedMemorySize, SMEM_BYTES);

    // launch order chosen so ncu's "-s 5 -c 1" profiles lstm_persistent (6th launch)
    mask_kernel<<<(NB * NT * 32) / 256, 256>>>(x);
    prep_weights<<<(NKD * NG) / 256, 256>>>(W, U, b);
    prep_x<<<(int)(((long)NB * NT * NF) / 256), 256>>>(x);
    prep_mlp<<<(2048 * NH) / 256, 256>>>(W1);
    init_state<<<(NB * NH) / 256, 256>>>();
    lstm_persistent<<<dim3(NG / BN, NB / BM), 256, SMEM_BYTES>>>();
    mlp1_kernel<<<dim3(NH / 64, NB / 64), 256>>>(b1);
    mlp2_kernel<<<NB, 64>>>(W2, b2, out);
}

// round 5
// speedup vs baseline: 1.8308x; 1.3609x over previous
#include <cuda_runtime.h>
#include <cuda_fp16.h>
#include <cstdint>

// Problem dims
constexpr int NB = 256, NT = 512, NF = 256, NH = 1024, NG = 4096;
constexpr int NKD = NH + NF; // 1280
constexpr int NOUT = 64;

// Persistent step-GEMM tiling (fp16 mma.sync m16n8k16)
constexpr int BM = 64, BN = 128, BK = 128;
constexpr int NKT = NKD / BK;  // 10
constexpr int NST = 3;
constexpr int AS_H = 144;      // A row stride in halves (288B -> conflict-free LDS.64)
constexpr int BS_H = 144;      // B row stride in halves
constexpr int A_H = BM * AS_H; // 9216 halves
constexpr int B_H = BN * BS_H; // 18432 halves
constexpr int ST_H = A_H + B_H;// 27648 halves / stage
constexpr int ZS_S = 136;
constexpr int SMEM_BYTES = NST * ST_H * 2 + BM * ZS_S * 4; // 200704
constexpr int NCTAS = (NB / BM) * (NG / BN);               // 128

// per-16 k permutation: position q holds k = PERM[q]; PINV is the inverse
__device__ __constant__ int c_perm[16] = {0,1,8,9, 2,3,10,11, 4,5,12,13, 6,7,14,15};
__device__ __constant__ int c_pinv[16] = {0,1,4,5, 8,9,12,13, 2,3,6,7, 10,11,14,15};

// ---------------- device scratch (allocation-free contract) ----------------
__device__ __half g_Mh[(long)NKD * NG];       // 10 MB fp16 interleaved+permuted [[U];[W]]
__device__ float  g_bI[NG];                   // interleaved bias
__device__ __half g_xh[(long)NB * NT * NF];   // 67 MB fp16 permuted x
__device__ float  g_MLP[2048 * NH];           // [W1a+W1b ; W1c]
__device__ __half g_h[2][NB * NH];            // ping-pong hidden, fp16 permuted
__device__ float  g_c[NB * NH];               // cell state, fp32 unpermuted
__device__ float  g_hf[NB * NH];              // final h, fp32 unpermuted (for MLP)
__device__ float  g_y1[NB * NH];
__device__ unsigned char g_mask[NB * NT];
__device__ unsigned g_bar = 0, g_gen = 0;

// ---------------- helpers ----------------
__device__ __forceinline__ float fex2(float x) {
    float y; asm("ex2.approx.f32 %0, %1;" : "=f"(y) : "f"(x)); return y;
}
__device__ __forceinline__ float frcp(float x) {
    float y; asm("rcp.approx.f32 %0, %1;" : "=f"(y) : "f"(x)); return y;
}
__device__ __forceinline__ float sigmf(float x) {
    return frcp(1.0f + fex2(-1.4426950408889634f * x));
}
__device__ __forceinline__ float tanhfa(float x) {
    return 1.0f - 2.0f * frcp(1.0f + fex2(2.8853900817779268f * x));
}
__device__ __forceinline__ void cp16(const __half* dst, const __half* src) {
    unsigned d = (unsigned)__cvta_generic_to_shared(dst);
    asm volatile("cp.async.cg.shared.global [%0], [%1], 16;" :: "r"(d), "l"(src));
}
__device__ __forceinline__ void cp_commit() { asm volatile("cp.async.commit_group;"); }
template <int N>
__device__ __forceinline__ void cp_wait() {
    asm volatile("cp.async.wait_group %0;" :: "n"(N));
}
__device__ __forceinline__ void mma16(float* d, unsigned a0, unsigned a1, unsigned a2,
                                      unsigned a3, unsigned b0, unsigned b1) {
    asm volatile(
        "mma.sync.aligned.m16n8k16.row.col.f32.f16.f16.f32 "
        "{%0,%1,%2,%3}, {%4,%5,%6,%7}, {%8,%9}, {%0,%1,%2,%3};"
        : "+f"(d[0]), "+f"(d[1]), "+f"(d[2]), "+f"(d[3])
        : "r"(a0), "r"(a1), "r"(a2), "r"(a3), "r"(b0), "r"(b1));
}

// grid barrier: 128 CTAs, all co-resident (1 CTA/SM at 196 KB smem)
__device__ __forceinline__ void grid_barrier() {
    __syncthreads();
    if (threadIdx.x == 0) {
        unsigned gen = *(volatile unsigned*)&g_gen;
        __threadfence();
        if (atomicAdd(&g_bar, 1u) == NCTAS - 1) {
            atomicExch(&g_bar, 0u);
            __threadfence();
            atomicAdd(&g_gen, 1u);
        } else {
            while (*(volatile unsigned*)&g_gen == gen) __nanosleep(64);
        }
        __threadfence();
    }
    __syncthreads();
}

// ---------------- prep kernels ----------------
__global__ void __launch_bounds__(256) mask_kernel(const float* __restrict__ x) {
    int warp = (blockIdx.x * 256 + threadIdx.x) >> 5;
    int lane = threadIdx.x & 31;
    if (warp >= NB * NT) return;
    const float4* p = (const float4*)(x + (long)warp * NF);
    float4 v1 = p[lane];
    float4 v2 = p[lane + 32];
    bool nz = v1.x != 0.f || v1.y != 0.f || v1.z != 0.f || v1.w != 0.f ||
              v2.x != 0.f || v2.y != 0.f || v2.z != 0.f || v2.w != 0.f;
    unsigned m = __ballot_sync(0xffffffffu, nz);
    if (lane == 0) g_mask[warp] = (m != 0u);
}

// g_Mh[n][pos] = fp16( perm-k of: k<NH ? U[k][g*NH+j] : W[k-NH][g*NH+j] ), n = 4j+g
__global__ void __launch_bounds__(256) prep_weights(
    const float* __restrict__ W, const float* __restrict__ U, const float* __restrict__ b) {
    int pos = blockIdx.x * 256 + threadIdx.x;
    int n = blockIdx.y;
    if (pos >= NKD) return;
    int k = (pos & ~15) | c_perm[pos & 15];
    int gate = n & 3, j = n >> 2;
    float v = (k < NH) ? U[(long)k * NG + gate * NH + j]
                       : W[(long)(k - NH) * NG + gate * NH + j];
    g_Mh[(long)n * NKD + pos] = __float2half_rn(v);
    if (pos == 0) g_bI[n] = b[gate * NH + j];
}

// fused: x->fp16 perm, MLP weight combine, state init
__global__ void __launch_bounds__(256) prep_misc(
    const float* __restrict__ x, const float* __restrict__ W1) {
    long idx = (long)blockIdx.x * 256 + threadIdx.x;
    const long N0 = (long)NB * NT * NF;      // x region
    const long N1 = (long)2048 * NH;         // mlp region
    const long N2 = (long)NB * NH;           // state region
    if (idx < N0) {
        long row = idx >> 8;
        int pos = (int)(idx & 255);
        int k = (pos & ~15) | c_perm[pos & 15];
        g_xh[idx] = __float2half_rn(x[(row << 8) + k]);
    } else if (idx < N0 + N1) {
        long r = idx - N0;
        int k = (int)(r >> 10), m = (int)(r & (NH - 1));
        float v = (k < NH) ? (W1[(long)k * NH + m] + W1[(long)(k + NH) * NH + m])
                           : (float)W1[(long)(k + NH) * NH + m];
        g_MLP[r] = v;
    } else if (idx < N0 + N1 + N2) {
        long r = idx - N0 - N1;
        g_h[0][r] = __float2half_rn(0.0f);
        g_c[r] = 0.0f;
    }
}

// ---------------- persistent LSTM recurrence (fp16 GEMM) ----------------
__global__ void __launch_bounds__(256) lstm_persistent() {
    extern __shared__ __half sh[];
    float* zs = (float*)(sh + NST * ST_H);  // [64][136]

    const int tid = threadIdx.x;
    const int lane = tid & 31;
    const int w = tid >> 5;
    const int wm = w & 1;   // 2 warps over M
    const int wn = w >> 1;  // 4 warps over N
    const int bn = blockIdx.x * BN;
    const int bm = blockIdx.y * BM;
    const int g = lane >> 2, c = lane & 3;

    // loader maps
    const int a_m = tid >> 2, a_q = tid & 3;   // A: row a_m, 16B-chunks a_q+4i (i<4)
    const int b_r = tid >> 1, b_q = tid & 1;   // B: row b_r, chunks b_q+2i (i<8)

    auto loadB = [&](int kt, int s) {
        __half* Bd = sh + s * ST_H + A_H + b_r * BS_H;
        const __half* src = g_Mh + (long)(bn + b_r) * NKD + kt * BK;
#pragma unroll
        for (int i = 0; i < 8; ++i) {
            int ch = b_q + 2 * i;
            cp16(Bd + 8 * ch, src + 8 * ch);
        }
    };
    auto loadA = [&](int kt, int s, const __half* hsrc, int t) {
        __half* Ad = sh + s * ST_H + a_m * AS_H;
        const __half* src = (kt < 8)
            ? (hsrc + (long)(bm + a_m) * NH + kt * BK)
            : (g_xh + ((long)(bm + a_m) * NT + t) * NF + (kt - 8) * BK);
#pragma unroll
        for (int i = 0; i < 4; ++i) {
            int ch = a_q + 4 * i;
            cp16(Ad + 8 * ch, src + 8 * ch);
        }
    };

    // pre-loop: B for t=0 stages 0,1 in flight (uncommitted)
    loadB(0, 0);
    loadB(1, 1);

    for (int t = 0; t < NT; ++t) {
        const int cur = t & 1;
        const __half* __restrict__ hsrc = g_h[cur];
        __half* __restrict__ hdst = g_h[cur ^ 1];

        loadA(0, 0, hsrc, t);
        cp_commit();                 // G0 = {B0, B1, A0}
        loadA(1, 1, hsrc, t);
        cp_commit();                 // G1 = {A1}

        float acc[2][4][4];
#pragma unroll
        for (int i = 0; i < 2; ++i)
#pragma unroll
            for (int j = 0; j < 4; ++j)
#pragma unroll
                for (int k = 0; k < 4; ++k) acc[i][j][k] = 0.0f;

        for (int kt = 0; kt < NKT; ++kt) {
            if (kt + 1 < NKT) cp_wait<1>(); else cp_wait<0>();
            __syncthreads();

            const __half* Ab = sh + (kt % NST) * ST_H;
            const __half* Bb = Ab + A_H;
            const __half* ar0 = Ab + (wm * 32 + g) * AS_H + 4 * c;
            const __half* br0 = Bb + (wn * 32 + g) * BS_H + 4 * c;
#pragma unroll
            for (int ch = 0; ch < 8; ++ch) {
                const int o = ch * 16;
                // A fragments: (a0,a2) from row r, (a1,a3) from row r+8
                uint2 aA = *(const uint2*)(ar0 + o);              // mt0 rows
                uint2 aB = *(const uint2*)(ar0 + 8 * AS_H + o);
                uint2 aC = *(const uint2*)(ar0 + 16 * AS_H + o);  // mt1 rows
                uint2 aD = *(const uint2*)(ar0 + 24 * AS_H + o);
                uint2 bb0 = *(const uint2*)(br0 + o);
                uint2 bb1 = *(const uint2*)(br0 + 8 * BS_H + o);
                uint2 bb2 = *(const uint2*)(br0 + 16 * BS_H + o);
                uint2 bb3 = *(const uint2*)(br0 + 24 * BS_H + o);
                mma16(acc[0][0], aA.x, aB.x, aA.y, aB.y, bb0.x, bb0.y);
                mma16(acc[0][1], aA.x, aB.x, aA.y, aB.y, bb1.x, bb1.y);
                mma16(acc[0][2], aA.x, aB.x, aA.y, aB.y, bb2.x, bb2.y);
                mma16(acc[0][3], aA.x, aB.x, aA.y, aB.y, bb3.x, bb3.y);
                mma16(acc[1][0], aC.x, aD.x, aC.y, aD.y, bb0.x, bb0.y);
                mma16(acc[1][1], aC.x, aD.x, aC.y, aD.y, bb1.x, bb1.y);
                mma16(acc[1][2], aC.x, aD.x, aC.y, aD.y, bb2.x, bb2.y);
                mma16(acc[1][3], aC.x, aD.x, aC.y, aD.y, bb3.x, bb3.y);
            }

            if (kt + 2 < NKT) {
                loadA(kt + 2, (kt + 2) % NST, hsrc, t);
                loadB(kt + 2, (kt + 2) % NST);
                cp_commit();
            }
        }

        // park z tile (gate-interleaved cols)
        {
            const int c2 = 2 * c;
#pragma unroll
            for (int mt = 0; mt < 2; ++mt)
#pragma unroll
                for (int nt = 0; nt < 4; ++nt) {
                    int r0 = wm * 32 + mt * 16 + g;
                    int c0 = wn * 32 + nt * 8 + c2;
                    zs[r0 * ZS_S + c0] = acc[mt][nt][0];
                    zs[r0 * ZS_S + c0 + 1] = acc[mt][nt][1];
                    zs[(r0 + 8) * ZS_S + c0] = acc[mt][nt][2];
                    zs[(r0 + 8) * ZS_S + c0 + 1] = acc[mt][nt][3];
                }
        }
        __syncthreads();  // z visible; all warps done with every stage

        // next step's B prefetch (t-independent), uncommitted until next step
        if (t + 1 < NT) {
            loadB(0, 0);
            loadB(1, 1);
        }

        // fused gate + state update epilogue
#pragma unroll
        for (int it = 0; it < 8; ++it) {
            int idx = it * 256 + tid;
            int bl = idx >> 5;  // local batch row 0..63
            int u = idx & 31;   // local unit 0..31
            int bg = bm + bl;
            int j = (bn >> 2) + u;              // unit index 0..1023
            int p = (j & ~15) | c_pinv[j & 15]; // permuted h position
            float4 z = *(float4*)(zs + bl * ZS_S + 4 * u);
            float4 bb = *(const float4*)(g_bI + bn + 4 * u);
            float iv = sigmf(z.x + bb.x);
            float fv = sigmf(z.y + bb.y);
            float gv = tanhfa(z.z + bb.z);
            float ov = sigmf(z.w + bb.w);
            long coff = (long)bg * NH + j;
            long hoff = (long)bg * NH + p;
            float co = g_c[coff];
            float ho = __half2float(hsrc[hoff]);
            float cn = fv * co + iv * gv;
            float hn = ov * tanhfa(cn);
            if (!g_mask[bg * NT + t]) { cn = co; hn = ho; }
            g_c[coff] = cn;
            hdst[hoff] = __float2half_rn(hn);
        }

        grid_barrier();
    }
}

// un-permute final h to fp32 for the MLP head
__global__ void __launch_bounds__(256) unperm_h() {
    int idx = blockIdx.x * 256 + threadIdx.x; // NB*NH
    int b = idx >> 10, j = idx & 1023;
    int p = (j & ~15) | c_pinv[j & 15];
    g_hf[idx] = __half2float(g_h[0][(b << 10) | p]);
}

// ---------------- MLP head ----------------
__global__ void __launch_bounds__(256) mlp1_kernel(const float* __restrict__ b1) {
    __shared__ float a_s[64 * 20];
    __shared__ float b_s[16 * 68];
    int tid = threadIdx.x;
    int bn = blockIdx.x * 64, bm = blockIdx.y * 64;
    int ty = tid >> 4, tx = tid & 15;
    float acc[4][4];
#pragma unroll
    for (int i = 0; i < 4; ++i)
#pragma unroll
        for (int j = 0; j < 4; ++j) acc[i][j] = 0.0f;

    for (int kt = 0; kt < 128; ++kt) {
        int k0 = kt * 16;
        {
            int m = tid >> 2, kq = tid & 3;
            int k = k0 + 4 * kq;
            const float* src = (k < NH) ? (g_hf + (long)(bm + m) * NH + k)
                                        : (g_c + (long)(bm + m) * NH + (k - NH));
            *(float4*)(a_s + m * 20 + 4 * kq) = *(const float4*)src;
        }
        {
            int kr = tid >> 4, c4 = tid & 15;
            *(float4*)(b_s + kr * 68 + 4 * c4) =
                *(const float4*)(g_MLP + (long)(k0 + kr) * NH + bn + 4 * c4);
        }
        __syncthreads();
#pragma unroll
        for (int k = 0; k < 16; ++k) {
            float ar[4], br[4];
#pragma unroll
            for (int i = 0; i < 4; ++i) {
                ar[i] = a_s[(4 * ty + i) * 20 + k];
                br[i] = b_s[k * 68 + 4 * tx + i];
            }
#pragma unroll
            for (int i = 0; i < 4; ++i)
#pragma unroll
                for (int j = 0; j < 4; ++j) acc[i][j] += ar[i] * br[j];
        }
        __syncthreads();
    }
#pragma unroll
    for (int i = 0; i < 4; ++i)
#pragma unroll
        for (int j = 0; j < 4; ++j) {
            float v = acc[i][j] + b1[bn + 4 * tx + j];
            v = v > 0.0f ? v : 0.2f * v;
            g_y1[(long)(bm + 4 * ty + i) * NH + bn + 4 * tx + j] = v;
        }
}

__global__ void __launch_bounds__(64) mlp2_kernel(
    const float* __restrict__ W2, const float* __restrict__ b2, float* __restrict__ out) {
    __shared__ float row[NH];
    int bg = blockIdx.x;
    int o = threadIdx.x;
    for (int i = o; i < NH; i += 64) row[i] = g_y1[(long)bg * NH + i];
    __syncthreads();
    float acc = b2[o];
#pragma unroll 8
    for (int k = 0; k < NH; ++k) acc += row[k] * W2[(long)k * NOUT + o];
    out[(long)bg * NOUT + o] = acc;
}

// ---------------- launch ----------------
extern "C" void kernel_launch(void* const* d_in, const int* in_sizes, int n_in,
                              void* d_out, int out_size) {
    const float* x  = (const float*)d_in[0];
    const float* W  = (const float*)d_in[1];
    const float* U  = (const float*)d_in[2];
    const float* b  = (const float*)d_in[3];
    const float* W1 = (const float*)d_in[4];
    const float* b1 = (const float*)d_in[5];
    const float* W2 = (const float*)d_in[6];
    const float* b2 = (const float*)d_in[7];
    float* out = (float*)d_out;

    cudaFuncSetAttribute(lstm_persistent,
                         cudaFuncAttributeMaxDynamicSharedMemorySize, SMEM_BYTES);

    const long MISC_N = (long)NB * NT * NF + (long)2048 * NH + (long)NB * NH;

    // lstm_persistent is the 4th launch (ncu profiles launch index 3)
    mask_kernel<<<(NB * NT * 32) / 256, 256>>>(x);
    prep_weights<<<dim3((NKD + 255) / 256, NG), 256>>>(W, U, b);
    prep_misc<<<(int)((MISC_N + 255) / 256), 256>>>(x, W1);
    lstm_persistent<<<dim3(NG / BN, NB / BM), 256, SMEM_BYTES>>>();
    unperm_h<<<(NB * NH) / 256, 256>>>();
    mlp1_kernel<<<dim3(NH / 64, NB / 64), 256>>>(b1);
    mlp2_kernel<<<NB, 64>>>(W2, b2, out);
}

// round 6
// speedup vs baseline: 2.5782x; 1.4082x over previous
#include <cuda_runtime.h>
#include <cuda_fp16.h>
#include <cstdint>

// Problem dims
constexpr int NB = 256, NT = 512, NF = 256, NH = 1024, NG = 4096;
constexpr int NKD = NH + NF; // 1280
constexpr int NOUT = 64;

// Persistent step-GEMM tiling (fp16 mma.sync + cp.async.bulk stage loads)
constexpr int BM = 64, BN = 128, BK = 128;
constexpr int NKT = NKD / BK;   // 10 (kt 0..7 = h blocks, 8..9 = x blocks)
constexpr int NST = 3;
constexpr int A_BY = BM * BK * 2;        // 16384 B
constexpr int B_BY = BN * BK * 2;        // 32768 B
constexpr int ST_BY = A_BY + B_BY;       // 49152 B
constexpr int ST_H = ST_BY / 2;          // halves
constexpr int A_H = A_BY / 2;            // 8192 halves
constexpr int ZS_S = 136;
constexpr int SMEM_BYTES = NST * ST_BY + BM * ZS_S * 4; // 182272
constexpr int NCTAS = (NB / BM) * (NG / BN);            // 128

// per-16 k permutation: position q holds k = PERM[q]
__device__ __constant__ int c_perm[16] = {0,1,8,9, 2,3,10,11, 4,5,12,13, 6,7,14,15};
__device__ __constant__ int c_pinv[16] = {0,1,4,5, 8,9,12,13, 2,3,6,7, 10,11,14,15};

// ---------------- device scratch (allocation-free contract) ----------------
// Block layouts, swizzled at 16-half granularity: chunk' = chunk ^ (row & 7)
__device__ __half g_MB[(long)NKT * NG * BK];     // [kt][n][128]
__device__ __half g_xB[(long)NT * 2 * NB * BK];  // [t][kb][b][128]
__device__ __half g_h[2][8 * NB * BK];           // [kb][b][128] ping-pong
__device__ float  g_bI[NG];
__device__ float  g_MLP[2048 * NH];
__device__ float  g_c[NB * NH];
__device__ float  g_hf[NB * NH];
__device__ float  g_y1[NB * NH];
__device__ unsigned char g_mask[NB * NT];
__device__ unsigned g_bar = 0, g_gen = 0;

// ---------------- helpers ----------------
__device__ __forceinline__ unsigned smem_u32(const void* p) {
    unsigned a;
    asm("{ .reg .u64 t; cvta.to.shared.u64 t, %1; cvt.u32.u64 %0, t; }" : "=r"(a) : "l"(p));
    return a;
}
__device__ __forceinline__ float fex2(float x) {
    float y; asm("ex2.approx.f32 %0, %1;" : "=f"(y) : "f"(x)); return y;
}
__device__ __forceinline__ float frcp(float x) {
    float y; asm("rcp.approx.f32 %0, %1;" : "=f"(y) : "f"(x)); return y;
}
__device__ __forceinline__ float sigmf(float x) {
    return frcp(1.0f + fex2(-1.4426950408889634f * x));
}
__device__ __forceinline__ float tanhfa(float x) {
    return 1.0f - 2.0f * frcp(1.0f + fex2(2.8853900817779268f * x));
}
__device__ __forceinline__ void mma16(float* d, unsigned a0, unsigned a1, unsigned a2,
                                      unsigned a3, unsigned b0, unsigned b1) {
    asm volatile(
        "mma.sync.aligned.m16n8k16.row.col.f32.f16.f16.f32 "
        "{%0,%1,%2,%3}, {%4,%5,%6,%7}, {%8,%9}, {%0,%1,%2,%3};"
        : "+f"(d[0]), "+f"(d[1]), "+f"(d[2]), "+f"(d[3])
        : "r"(a0), "r"(a1), "r"(a2), "r"(a3), "r"(b0), "r"(b1));
}
__device__ __forceinline__ void mbar_init(unsigned mbar, unsigned cnt) {
    asm volatile("mbarrier.init.shared.b64 [%0], %1;" :: "r"(mbar), "r"(cnt) : "memory");
}
__device__ __forceinline__ void mbar_inval(unsigned mbar) {
    asm volatile("mbarrier.inval.shared.b64 [%0];" :: "r"(mbar) : "memory");
}
__device__ __forceinline__ void mbar_expect_tx(unsigned mbar, unsigned bytes) {
    asm volatile("mbarrier.arrive.expect_tx.shared.b64 _, [%0], %1;"
                 :: "r"(mbar), "r"(bytes) : "memory");
}
__device__ __forceinline__ void mbar_wait(unsigned mbar, unsigned parity) {
    asm volatile(
        "{\n\t.reg .pred P;\n"
        "W%=:\n\t"
        "mbarrier.try_wait.parity.acquire.cta.shared::cta.b64 P, [%0], %1, 0x989680;\n\t"
        "@!P bra W%=;\n\t}"
        :: "r"(mbar), "r"(parity) : "memory");
}
__device__ __forceinline__ void bulk_g2s(unsigned dst, const void* src, unsigned bytes,
                                         unsigned mbar) {
    asm volatile(
        "cp.async.bulk.shared::cta.global.mbarrier::complete_tx::bytes [%0], [%1], %2, [%3];"
        :: "r"(dst), "l"(src), "r"(bytes), "r"(mbar) : "memory");
}

// grid barrier: 128 CTAs, all co-resident (1 CTA/SM at 178 KB smem)
__device__ __forceinline__ void grid_barrier() {
    __syncthreads();
    if (threadIdx.x == 0) {
        unsigned gen = *(volatile unsigned*)&g_gen;
        __threadfence();
        if (atomicAdd(&g_bar, 1u) == NCTAS - 1) {
            atomicExch(&g_bar, 0u);
            __threadfence();
            atomicAdd(&g_gen, 1u);
        } else {
            while (*(volatile unsigned*)&g_gen == gen) __nanosleep(64);
        }
        __threadfence();
    }
    __syncthreads();
}

// ---------------- prep kernels ----------------
__global__ void __launch_bounds__(256) mask_kernel(const float* __restrict__ x) {
    int warp = (blockIdx.x * 256 + threadIdx.x) >> 5;
    int lane = threadIdx.x & 31;
    if (warp >= NB * NT) return;
    const float4* p = (const float4*)(x + (long)warp * NF);
    float4 v1 = p[lane];
    float4 v2 = p[lane + 32];
    bool nz = v1.x != 0.f || v1.y != 0.f || v1.z != 0.f || v1.w != 0.f ||
              v2.x != 0.f || v2.y != 0.f || v2.z != 0.f || v2.w != 0.f;
    unsigned m = __ballot_sync(0xffffffffu, nz);
    if (lane == 0) g_mask[warp] = (m != 0u);
}

// g_MB[kt][n][hc_s] with swizzle key n&7 and per-16 perm inside chunks
__global__ void __launch_bounds__(256) prep_weights(
    const float* __restrict__ W, const float* __restrict__ U, const float* __restrict__ b) {
    long idx = (long)blockIdx.x * 256 + threadIdx.x; // NKT*NG*128 = 5242880
    int hs = (int)(idx & 127);
    int n = (int)((idx >> 7) & (NG - 1));
    int kt = (int)(idx >> 19);
    int cc = (hs >> 4) ^ (n & 7);
    int hc = (cc << 4) | (hs & 15);
    int kl = (hc & ~15) | c_perm[hc & 15];
    int k = kt * BK + kl;
    int gate = n & 3, j = n >> 2;
    float v = (k < NH) ? U[(long)k * NG + gate * NH + j]
                       : W[(long)(k - NH) * NG + gate * NH + j];
    g_MB[idx] = __float2half_rn(v);
    if (hs == 0 && kt == 0) g_bI[n] = b[gate * NH + j];
}

// fused: x -> block layout (chunk-vectorized), MLP weight combine, state init
__global__ void __launch_bounds__(256) prep_misc(
    const float* __restrict__ x, const float* __restrict__ W1) {
    const long N0 = (long)NT * 2 * NB * 8;  // x chunks (16 halves each) = 2097152
    const long N1 = (long)2048 * NH;        // 2097152
    const long N2 = (long)NB * NH;          // 262144
    long idx = (long)blockIdx.x * 256 + threadIdx.x;
    if (idx < N0) {
        int cs = (int)(idx & 7);
        int b = (int)((idx >> 3) & 255);
        int kb = (int)((idx >> 11) & 1);
        int t = (int)(idx >> 12);
        int cc = cs ^ (b & 7);
        const float* src = x + ((long)b * NT + t) * NF + kb * 128 + cc * 16;
        float4 v0 = *(const float4*)(src);
        float4 v1 = *(const float4*)(src + 4);
        float4 v2 = *(const float4*)(src + 8);
        float4 v3 = *(const float4*)(src + 12);
        __half2 h[8];
        h[0] = __floats2half2_rn(v0.x, v0.y);   // k 0,1
        h[1] = __floats2half2_rn(v2.x, v2.y);   // k 8,9
        h[2] = __floats2half2_rn(v0.z, v0.w);   // k 2,3
        h[3] = __floats2half2_rn(v2.z, v2.w);   // k 10,11
        h[4] = __floats2half2_rn(v1.x, v1.y);   // k 4,5
        h[5] = __floats2half2_rn(v3.x, v3.y);   // k 12,13
        h[6] = __floats2half2_rn(v1.z, v1.w);   // k 6,7
        h[7] = __floats2half2_rn(v3.z, v3.w);   // k 14,15
        __half* dst = g_xB + ((((long)t * 2 + kb) * NB + b) * 128 + cs * 16);
        *(uint4*)(dst) = *(uint4*)(h);
        *(uint4*)(dst + 8) = *(uint4*)(h + 4);
    } else if (idx < N0 + N1) {
        long r = idx - N0;
        int k = (int)(r >> 10), m = (int)(r & (NH - 1));
        float v = (k < NH) ? (W1[(long)k * NH + m] + W1[(long)(k + NH) * NH + m])
                           : W1[(long)(k + NH) * NH + m];
        g_MLP[r] = v;
    } else if (idx < N0 + N1 + N2) {
        long r = idx - N0 - N1;
        g_c[r] = 0.0f;
        g_h[0][r] = __float2half_rn(0.0f);
    }
}

// ---------------- persistent LSTM recurrence ----------------
__global__ void __launch_bounds__(256) lstm_persistent() {
    extern __shared__ __align__(128) char dsm[];
    __half* sh = (__half*)dsm;
    float* zs = (float*)(dsm + NST * ST_BY);
    __shared__ __align__(8) unsigned long long s_mbar[NST];

    const int tid = threadIdx.x;
    const int lane = tid & 31;
    const int w = tid >> 5;
    const int wm = w & 1;   // 2 warps over M
    const int wn = w >> 1;  // 4 warps over N
    const int bn = blockIdx.x * BN;
    const int bm = blockIdx.y * BM;
    const int g = lane >> 2;
    const int c4 = 4 * (lane & 3);

    const unsigned smb = smem_u32(sh);
    const unsigned mbb = smem_u32(s_mbar);

    if (tid == 0)
        for (int s = 0; s < NST; ++s) mbar_init(mbb + 8 * s, 1);
    __syncthreads();

    int ph[NST] = {0, 0, 0};

    for (int t = 0; t < NT; ++t) {
        const int cur = t & 1;
        const __half* __restrict__ hsrc = g_h[cur];
        __half* __restrict__ hdst = g_h[cur ^ 1];

        // issue fills for kt 0,1 (thread 0 only; 1 expect_tx + 2 bulk ops each)
        auto fill = [&](int kt, int s) {
            unsigned mb = mbb + 8 * s;
            mbar_expect_tx(mb, (unsigned)ST_BY);
            const __half* asrc = (kt < 8)
                ? (hsrc + ((long)kt * NB + bm) * BK)
                : (g_xB + (((long)t * 2 + (kt - 8)) * NB + bm) * BK);
            bulk_g2s(smb + s * ST_BY, asrc, A_BY, mb);
            const __half* bsrc = g_MB + ((long)kt * NG + bn) * BK;
            bulk_g2s(smb + s * ST_BY + A_BY, bsrc, B_BY, mb);
        };
        if (tid == 0) { fill(0, 0); fill(1, 1); }

        // prefetch epilogue state (c, old h, mask) — overlaps the whole GEMM
        float co8[8], ho8[8];
        int hpos8[8];
        unsigned mbits = 0;
#pragma unroll
        for (int it = 0; it < 8; ++it) {
            int idx = it * 256 + tid;
            int bl = idx >> 5, u = idx & 31;
            int bg = bm + bl;
            int j = (bn >> 2) + u;
            co8[it] = __ldg(g_c + (long)bg * NH + j);
            int q = (j & ~15) | c_pinv[j & 15];
            int kb = q >> 7, hc = q & 127;
            int hoff = (int)((((long)kb * NB + bg) << 7) +
                             (((hc >> 4) ^ (bg & 7)) << 4) + (hc & 15));
            hpos8[it] = hoff;
            ho8[it] = __half2float(__ldg(hsrc + hoff));
            mbits |= (unsigned)(g_mask[bg * NT + t] != 0) << it;
        }

        float acc[2][4][4];
#pragma unroll
        for (int i = 0; i < 2; ++i)
#pragma unroll
            for (int j = 0; j < 4; ++j)
#pragma unroll
                for (int k = 0; k < 4; ++k) acc[i][j][k] = 0.0f;

        for (int kt = 0; kt < NKT; ++kt) {
            const int s = kt % NST;
            mbar_wait(mbb + 8 * s, (unsigned)ph[s]);
            ph[s] ^= 1;
            __syncthreads();  // all warps finished kt-1 -> stage (kt+2)%3 reusable
            if (tid == 0 && kt + 2 < NKT) fill(kt + 2, (kt + 2) % NST);

            const __half* Ab = sh + s * ST_H;
            const __half* Bb = Ab + A_H;
            const __half* arow = Ab + (wm * 32 + g) * BK;
            const __half* brow = Bb + (wn * 32 + g) * BK;
#pragma unroll
            for (int ch = 0; ch < 8; ++ch) {
                const int o = ((ch ^ g) << 4) + c4;  // swizzled chunk + lane offset
                uint2 aA = *(const uint2*)(arow + o);
                uint2 aB = *(const uint2*)(arow + 1024 + o);
                uint2 aC = *(const uint2*)(arow + 2048 + o);
                uint2 aD = *(const uint2*)(arow + 3072 + o);
                uint2 b0 = *(const uint2*)(brow + o);
                uint2 b1 = *(const uint2*)(brow + 1024 + o);
                uint2 b2 = *(const uint2*)(brow + 2048 + o);
                uint2 b3 = *(const uint2*)(brow + 3072 + o);
                mma16(acc[0][0], aA.x, aB.x, aA.y, aB.y, b0.x, b0.y);
                mma16(acc[0][1], aA.x, aB.x, aA.y, aB.y, b1.x, b1.y);
                mma16(acc[0][2], aA.x, aB.x, aA.y, aB.y, b2.x, b2.y);
                mma16(acc[0][3], aA.x, aB.x, aA.y, aB.y, b3.x, b3.y);
                mma16(acc[1][0], aC.x, aD.x, aC.y, aD.y, b0.x, b0.y);
                mma16(acc[1][1], aC.x, aD.x, aC.y, aD.y, b1.x, b1.y);
                mma16(acc[1][2], aC.x, aD.x, aC.y, aD.y, b2.x, b2.y);
                mma16(acc[1][3], aC.x, aD.x, aC.y, aD.y, b3.x, b3.y);
            }
        }

        // park z tile (gate-interleaved cols)
        {
            const int c2 = c4 >> 1;
#pragma unroll
            for (int mt = 0; mt < 2; ++mt)
#pragma unroll
                for (int nt = 0; nt < 4; ++nt) {
                    int r0 = wm * 32 + mt * 16 + g;
                    int c0 = wn * 32 + nt * 8 + c2;
                    zs[r0 * ZS_S + c0] = acc[mt][nt][0];
                    zs[r0 * ZS_S + c0 + 1] = acc[mt][nt][1];
                    zs[(r0 + 8) * ZS_S + c0] = acc[mt][nt][2];
                    zs[(r0 + 8) * ZS_S + c0 + 1] = acc[mt][nt][3];
                }
        }
        __syncthreads();

        // fused gate + state update epilogue
#pragma unroll
        for (int it = 0; it < 8; ++it) {
            int idx = it * 256 + tid;
            int bl = idx >> 5, u = idx & 31;
            int bg = bm + bl;
            int j = (bn >> 2) + u;
            float4 z = *(float4*)(zs + bl * ZS_S + 4 * u);
            float4 bb = *(const float4*)(g_bI + bn + 4 * u);
            float iv = sigmf(z.x + bb.x);
            float fv = sigmf(z.y + bb.y);
            float gv = tanhfa(z.z + bb.z);
            float ov = sigmf(z.w + bb.w);
            float cn = fv * co8[it] + iv * gv;
            float hn = ov * tanhfa(cn);
            if (!((mbits >> it) & 1u)) { cn = co8[it]; hn = ho8[it]; }
            g_c[(long)bg * NH + j] = cn;
            hdst[hpos8[it]] = __float2half_rn(hn);
        }

        grid_barrier();
    }

    if (tid == 0)
        for (int s = 0; s < NST; ++s) mbar_inval(mbb + 8 * s);
}

// un-permute/un-swizzle final h to fp32 for the MLP head
__global__ void __launch_bounds__(256) unperm_h() {
    int idx = blockIdx.x * 256 + threadIdx.x; // NB*NH
    int b = idx >> 10, j = idx & 1023;
    int q = (j & ~15) | c_pinv[j & 15];
    int kb = q >> 7, hc = q & 127;
    long off = (((long)kb * NB + b) << 7) + (((hc >> 4) ^ (b & 7)) << 4) + (hc & 15);
    g_hf[idx] = __half2float(g_h[0][off]);
}

// ---------------- MLP head ----------------
__global__ void __launch_bounds__(256) mlp1_kernel(const float* __restrict__ b1) {
    __shared__ float a_s[64 * 20];
    __shared__ float b_s[16 * 68];
    int tid = threadIdx.x;
    int bn = blockIdx.x * 64, bm = blockIdx.y * 64;
    int ty = tid >> 4, tx = tid & 15;
    float acc[4][4];
#pragma unroll
    for (int i = 0; i < 4; ++i)
#pragma unroll
        for (int j = 0; j < 4; ++j) acc[i][j] = 0.0f;

    for (int kt = 0; kt < 128; ++kt) {
        int k0 = kt * 16;
        {
            int m = tid >> 2, kq = tid & 3;
            int k = k0 + 4 * kq;
            const float* src = (k < NH) ? (g_hf + (long)(bm + m) * NH + k)
                                        : (g_c + (long)(bm + m) * NH + (k - NH));
            *(float4*)(a_s + m * 20 + 4 * kq) = *(const float4*)src;
        }
        {
            int kr = tid >> 4, cq = tid & 15;
            *(float4*)(b_s + kr * 68 + 4 * cq) =
                *(const float4*)(g_MLP + (long)(k0 + kr) * NH + bn + 4 * cq);
        }
        __syncthreads();
#pragma unroll
        for (int k = 0; k < 16; ++k) {
            float ar[4], br[4];
#pragma unroll
            for (int i = 0; i < 4; ++i) {
                ar[i] = a_s[(4 * ty + i) * 20 + k];
                br[i] = b_s[k * 68 + 4 * tx + i];
            }
#pragma unroll
            for (int i = 0; i < 4; ++i)
#pragma unroll
                for (int j = 0; j < 4; ++j) acc[i][j] += ar[i] * br[j];
        }
        __syncthreads();
    }
#pragma unroll
    for (int i = 0; i < 4; ++i)
#pragma unroll
        for (int j = 0; j < 4; ++j) {
            float v = acc[i][j] + b1[bn + 4 * tx + j];
            v = v > 0.0f ? v : 0.2f * v;
            g_y1[(long)(bm + 4 * ty + i) * NH + bn + 4 * tx + j] = v;
        }
}

__global__ void __launch_bounds__(64) mlp2_kernel(
    const float* __restrict__ W2, const float* __restrict__ b2, float* __restrict__ out) {
    __shared__ float row[NH];
    int bg = blockIdx.x;
    int o = threadIdx.x;
    for (int i = o; i < NH; i += 64) row[i] = g_y1[(long)bg * NH + i];
    __syncthreads();
    float acc = b2[o];
#pragma unroll 8
    for (int k = 0; k < NH; ++k) acc += row[k] * W2[(long)k * NOUT + o];
    out[(long)bg * NOUT + o] = acc;
}

// ---------------- launch ----------------
extern "C" void kernel_launch(void* const* d_in, const int* in_sizes, int n_in,
                              void* d_out, int out_size) {
    const float* x  = (const float*)d_in[0];
    const float* W  = (const float*)d_in[1];
    const float* U  = (const float*)d_in[2];
    const float* b  = (const float*)d_in[3];
    const float* W1 = (const float*)d_in[4];
    const float* b1 = (const float*)d_in[5];
    const float* W2 = (const float*)d_in[6];
    const float* b2 = (const float*)d_in[7];
    float* out = (float*)d_out;

    cudaFuncSetAttribute(lstm_persistent,
                         cudaFuncAttributeMaxDynamicSharedMemorySize, SMEM_BYTES);

    const long WN = (long)NKT * NG * 128;                       // 5242880
    const long MN = (long)NT * 2 * NB * 8 + (long)2048 * NH + (long)NB * NH;

    // lstm_persistent is the 4th launch (ncu profiles launch index 3)
    mask_kernel<<<(NB * NT * 32) / 256, 256>>>(x);
    prep_weights<<<(int)(WN / 256), 256>>>(W, U, b);
    prep_misc<<<(int)((MN + 255) / 256), 256>>>(x, W1);
    lstm_persistent<<<dim3(NG / BN, NB / BM), 256, SMEM_BYTES>>>();
    unperm_h<<<(NB * NH) / 256, 256>>>();
    mlp1_kernel<<<dim3(NH / 64, NB / 64), 256>>>(b1);
    mlp2_kernel<<<NB, 64>>>(W2, b2, out);
}